// round 2
// baseline (speedup 1.0000x reference)
#include <cuda_runtime.h>
#include <math.h>

#define NTHR    256
#define BM      64
#define TM      4
#define TN      8
#define MROWS   400000
#define NBAG    8
#define NPER    50000
#define DIN     256
#define HDIM    128
#define NCHUNK  391              // ceil(50000/128)
#define INV_TAU (1.0f/0.3f)
#define LN_EPS  1e-5f

// scratch (static device globals; no runtime allocation)
__device__ float g_h2[(size_t)MROWS * HDIM];     // 204.8 MB
__device__ float g_scores[MROWS];
__device__ float g_bagmax[NBAG];
__device__ float g_pvec[NBAG * NCHUNK * HDIM];
__device__ float g_pZ[NBAG * NCHUNK];

// reduce over the 16 lanes sharing the same ty (lanes differ only in bits 0..3)
__device__ __forceinline__ float hreduce16(float v) {
    v += __shfl_xor_sync(0xffffffffu, v, 8);
    v += __shfl_xor_sync(0xffffffffu, v, 4);
    v += __shfl_xor_sync(0xffffffffu, v, 2);
    v += __shfl_xor_sync(0xffffffffu, v, 1);
    return v;
}

// Fused per-row pipeline: h1 = relu(LN(x@W1+b1)); h2 = relu(LN(h1@W2+b2));
// a = tanh(h2@Wa1+ba1); score = a@Wa2 + ba2. Writes g_h2 and g_scores.
// Tile: BM=64 rows x 128 cols, 256 threads, thread tile 4x8.
__global__ __launch_bounds__(NTHR)
void k_rows(const float* __restrict__ x,
            const float* __restrict__ W1, const float* __restrict__ b1,
            const float* __restrict__ g1, const float* __restrict__ be1,
            const float* __restrict__ W2, const float* __restrict__ b2,
            const float* __restrict__ g2, const float* __restrict__ be2,
            const float* __restrict__ Wa1, const float* __restrict__ ba1,
            const float* __restrict__ Wa2, const float* __restrict__ ba2)
{
    extern __shared__ float sm[];
    float* xs  = sm;               // [64][36]  (padded)
    float* ws  = xs + 64 * 36;     // [32][128] weight chunk
    float* h1s = ws + 32 * 128;    // [64][132] inter-GEMM tile

    const int tid  = threadIdx.x;
    const int ty   = tid >> 4;          // 0..15
    const int tx   = tid & 15;          // 0..15
    const int col0 = tx * TN;           // 0..120
    const long rowTile = (long)blockIdx.x * BM;

    float acc[TM][TN];
    const float invH = 1.0f / 128.0f;

    // ---------------- phase 1: GEMM1 (K=256) ----------------
#pragma unroll
    for (int i = 0; i < TM; i++)
#pragma unroll
        for (int j = 0; j < TN; j++) acc[i][j] = 0.0f;

    for (int k0 = 0; k0 < DIN; k0 += 32) {
        // stage x tile [64 x 32]
        for (int t = tid; t < 512; t += NTHR) {
            int r = t >> 3, q = t & 7;
            float4 v = *(const float4*)(x + (rowTile + r) * DIN + k0 + q * 4);
            *(float4*)(xs + r * 36 + q * 4) = v;
        }
        // stage W1 chunk [32 x 128]
        {
            const float* wp = W1 + (size_t)k0 * HDIM;
            for (int t = tid; t < 1024; t += NTHR)
                ((float4*)ws)[t] = ((const float4*)wp)[t];
        }
        __syncthreads();
#pragma unroll
        for (int k = 0; k < 32; k++) {
            float a[TM], b[TN];
#pragma unroll
            for (int i = 0; i < TM; i++) a[i] = xs[(ty * 4 + i) * 36 + k];
#pragma unroll
            for (int j = 0; j < TN; j++) b[j] = ws[k * 128 + col0 + j];
#pragma unroll
            for (int i = 0; i < TM; i++)
#pragma unroll
                for (int j = 0; j < TN; j++) acc[i][j] = fmaf(a[i], b[j], acc[i][j]);
        }
        __syncthreads();
    }

    // LN1 + ReLU
    {
        float bv[TN], gv[TN], ev[TN];
#pragma unroll
        for (int j = 0; j < TN; j++) { bv[j] = b1[col0 + j]; gv[j] = g1[col0 + j]; ev[j] = be1[col0 + j]; }
#pragma unroll
        for (int i = 0; i < TM; i++) {
            float s = 0.0f;
#pragma unroll
            for (int j = 0; j < TN; j++) { acc[i][j] += bv[j]; s += acc[i][j]; }
            s = hreduce16(s);
            float mu = s * invH;
            float v = 0.0f;
#pragma unroll
            for (int j = 0; j < TN; j++) { float d = acc[i][j] - mu; v = fmaf(d, d, v); }
            v = hreduce16(v);
            float inv = rsqrtf(v * invH + LN_EPS);
#pragma unroll
            for (int j = 0; j < TN; j++)
                acc[i][j] = fmaxf(fmaf((acc[i][j] - mu) * inv, gv[j], ev[j]), 0.0f);
        }
    }
    // write h1 tile to smem
#pragma unroll
    for (int i = 0; i < TM; i++) {
        int r = ty * 4 + i;
        *(float4*)(h1s + r * 132 + col0)     = make_float4(acc[i][0], acc[i][1], acc[i][2], acc[i][3]);
        *(float4*)(h1s + r * 132 + col0 + 4) = make_float4(acc[i][4], acc[i][5], acc[i][6], acc[i][7]);
    }
    __syncthreads();

    // ---------------- phase 2: GEMM2 (K=128), A = h1s ----------------
#pragma unroll
    for (int i = 0; i < TM; i++)
#pragma unroll
        for (int j = 0; j < TN; j++) acc[i][j] = 0.0f;

    for (int k0 = 0; k0 < HDIM; k0 += 32) {
        const float* wp = W2 + (size_t)k0 * HDIM;
        for (int t = tid; t < 1024; t += NTHR)
            ((float4*)ws)[t] = ((const float4*)wp)[t];
        __syncthreads();
#pragma unroll
        for (int k = 0; k < 32; k++) {
            float a[TM], b[TN];
#pragma unroll
            for (int i = 0; i < TM; i++) a[i] = h1s[(ty * 4 + i) * 132 + k0 + k];
#pragma unroll
            for (int j = 0; j < TN; j++) b[j] = ws[k * 128 + col0 + j];
#pragma unroll
            for (int i = 0; i < TM; i++)
#pragma unroll
                for (int j = 0; j < TN; j++) acc[i][j] = fmaf(a[i], b[j], acc[i][j]);
        }
        __syncthreads();
    }

    // LN2 + ReLU
    {
        float bv[TN], gv[TN], ev[TN];
#pragma unroll
        for (int j = 0; j < TN; j++) { bv[j] = b2[col0 + j]; gv[j] = g2[col0 + j]; ev[j] = be2[col0 + j]; }
#pragma unroll
        for (int i = 0; i < TM; i++) {
            float s = 0.0f;
#pragma unroll
            for (int j = 0; j < TN; j++) { acc[i][j] += bv[j]; s += acc[i][j]; }
            s = hreduce16(s);
            float mu = s * invH;
            float v = 0.0f;
#pragma unroll
            for (int j = 0; j < TN; j++) { float d = acc[i][j] - mu; v = fmaf(d, d, v); }
            v = hreduce16(v);
            float inv = rsqrtf(v * invH + LN_EPS);
#pragma unroll
            for (int j = 0; j < TN; j++)
                acc[i][j] = fmaxf(fmaf((acc[i][j] - mu) * inv, gv[j], ev[j]), 0.0f);
        }
    }

    // write h2 to global + back into h1s (reuse as A for GEMM3)
#pragma unroll
    for (int i = 0; i < TM; i++) {
        int r = ty * 4 + i;
        long row = rowTile + r;
        float4 v0 = make_float4(acc[i][0], acc[i][1], acc[i][2], acc[i][3]);
        float4 v1 = make_float4(acc[i][4], acc[i][5], acc[i][6], acc[i][7]);
        *(float4*)(g_h2 + row * HDIM + col0)     = v0;
        *(float4*)(g_h2 + row * HDIM + col0 + 4) = v1;
        *(float4*)(h1s + r * 132 + col0)     = v0;
        *(float4*)(h1s + r * 132 + col0 + 4) = v1;
    }
    __syncthreads();

    // ---------------- phase 3: attention GEMM (K=128) ----------------
#pragma unroll
    for (int i = 0; i < TM; i++)
#pragma unroll
        for (int j = 0; j < TN; j++) acc[i][j] = 0.0f;

    for (int k0 = 0; k0 < HDIM; k0 += 32) {
        const float* wp = Wa1 + (size_t)k0 * HDIM;
        for (int t = tid; t < 1024; t += NTHR)
            ((float4*)ws)[t] = ((const float4*)wp)[t];
        __syncthreads();
#pragma unroll
        for (int k = 0; k < 32; k++) {
            float a[TM], b[TN];
#pragma unroll
            for (int i = 0; i < TM; i++) a[i] = h1s[(ty * 4 + i) * 132 + k0 + k];
#pragma unroll
            for (int j = 0; j < TN; j++) b[j] = ws[k * 128 + col0 + j];
#pragma unroll
            for (int i = 0; i < TM; i++)
#pragma unroll
                for (int j = 0; j < TN; j++) acc[i][j] = fmaf(a[i], b[j], acc[i][j]);
        }
        __syncthreads();
    }

    // tanh + dot with Wa2 -> scores
    {
        float bav[TN], wv[TN];
#pragma unroll
        for (int j = 0; j < TN; j++) { bav[j] = ba1[col0 + j]; wv[j] = Wa2[col0 + j]; }
        float ba2v = ba2[0];
#pragma unroll
        for (int i = 0; i < TM; i++) {
            float s = 0.0f;
#pragma unroll
            for (int j = 0; j < TN; j++) s = fmaf(tanhf(acc[i][j] + bav[j]), wv[j], s);
            s = hreduce16(s);
            if (tx == 0) g_scores[rowTile + ty * 4 + i] = s + ba2v;
        }
    }
}

// per-bag score max (order-independent, deterministic)
__global__ __launch_bounds__(256)
void k_max()
{
    const int bag = blockIdx.x;
    const int tid = threadIdx.x;
    __shared__ float red[256];
    float m = -3.4e38f;
    const float* sp = g_scores + (size_t)bag * NPER;
    for (int i = tid; i < NPER; i += 256) m = fmaxf(m, sp[i]);
    red[tid] = m;
    __syncthreads();
    for (int off = 128; off; off >>= 1) {
        if (tid < off) red[tid] = fmaxf(red[tid], red[tid + off]);
        __syncthreads();
    }
    if (tid == 0) g_bagmax[bag] = red[0];
}

// per-chunk weighted partial sums: pvec[bag,chunk,:] = sum_n w_n * h2[n,:], pZ = sum_n w_n
__global__ __launch_bounds__(128)
void k_wsum()
{
    const int b = blockIdx.x / NCHUNK;
    const int c = blockIdx.x % NCHUNK;
    const int tid = threadIdx.x;
    const int base = c * 128;
    const int cnt = min(128, NPER - base);
    __shared__ float wrow[128];

    float w = 0.0f;
    if (tid < cnt)
        w = expf((g_scores[(size_t)b * NPER + base + tid] - g_bagmax[b]) * INV_TAU);
    wrow[tid] = w;
    __syncthreads();

    float acc = 0.0f;
    const float* hp = g_h2 + ((size_t)b * NPER + base) * HDIM + tid;
#pragma unroll 8
    for (int n = 0; n < cnt; n++)
        acc = fmaf(wrow[n], hp[(size_t)n * HDIM], acc);
    g_pvec[((size_t)b * NCHUNK + c) * HDIM + tid] = acc;

    __syncthreads();
    for (int off = 64; off; off >>= 1) {
        if (tid < off) wrow[tid] += wrow[tid + off];
        __syncthreads();
    }
    if (tid == 0) g_pZ[b * NCHUNK + c] = wrow[0];
}

// final: reduce partials -> bag vector -> classifier + risk heads
__global__ __launch_bounds__(128)
void k_final(const float* __restrict__ Wc1, const float* __restrict__ bc1,
             const float* __restrict__ Wc2, const float* __restrict__ bc2,
             const float* __restrict__ Ws1, const float* __restrict__ bs1,
             const float* __restrict__ Ws2, const float* __restrict__ bs2,
             float* __restrict__ out)
{
    const int bag = blockIdx.x;
    const int tid = threadIdx.x;
    __shared__ float bagn[128];
    __shared__ float hid[128];
    __shared__ float redz[128];
    __shared__ float hs[64];

    float v = 0.0f;
    for (int c = 0; c < NCHUNK; c++)
        v += g_pvec[((size_t)bag * NCHUNK + c) * HDIM + tid];

    float zp = 0.0f;
    for (int c = tid; c < NCHUNK; c += 128)
        zp += g_pZ[bag * NCHUNK + c];
    redz[tid] = zp;
    __syncthreads();
    for (int off = 64; off; off >>= 1) {
        if (tid < off) redz[tid] += redz[tid + off];
        __syncthreads();
    }
    const float Z = redz[0];
    bagn[tid] = v / Z;
    __syncthreads();

    // classifier hidden
    {
        float h = bc1[tid];
        for (int k = 0; k < 128; k++) h = fmaf(bagn[k], Wc1[k * 128 + tid], h);
        hid[tid] = fmaxf(h, 0.0f);
    }
    // risk hidden
    if (tid < 64) {
        float h = bs1[tid];
        for (int k = 0; k < 128; k++) h = fmaf(bagn[k], Ws1[k * 64 + tid], h);
        hs[tid] = fmaxf(h, 0.0f);
    }
    __syncthreads();

    if (tid < 2) {
        float s = bc2[tid];
        for (int j = 0; j < 128; j++) s = fmaf(hid[j], Wc2[j * 2 + tid], s);
        out[bag * 2 + tid] = s;            // logits [8,2] flattened first
    }
    if (tid == 2) {
        float r = bs2[0];
        for (int j = 0; j < 64; j++) r = fmaf(hs[j], Ws2[j], r);
        out[16 + bag] = r;                  // risk [8] after logits
    }
}

extern "C" void kernel_launch(void* const* d_in, const int* in_sizes, int n_in,
                              void* d_out, int out_size)
{
    const float* x   = (const float*)d_in[0];
    const float* W1  = (const float*)d_in[1];
    const float* b1  = (const float*)d_in[2];
    const float* g1  = (const float*)d_in[3];
    const float* be1 = (const float*)d_in[4];
    const float* W2  = (const float*)d_in[5];
    const float* b2  = (const float*)d_in[6];
    const float* g2  = (const float*)d_in[7];
    const float* be2 = (const float*)d_in[8];
    const float* Wa1 = (const float*)d_in[9];
    const float* ba1 = (const float*)d_in[10];
    const float* Wa2 = (const float*)d_in[11];
    const float* ba2 = (const float*)d_in[12];
    const float* Wc1 = (const float*)d_in[13];
    const float* bc1 = (const float*)d_in[14];
    const float* Wc2 = (const float*)d_in[15];
    const float* bc2 = (const float*)d_in[16];
    const float* Ws1 = (const float*)d_in[17];
    const float* bs1 = (const float*)d_in[18];
    const float* Ws2 = (const float*)d_in[19];
    const float* bs2 = (const float*)d_in[20];
    float* out = (float*)d_out;

    const int smem = (64 * 36 + 32 * 128 + 64 * 132) * 4;  // 59392 B
    cudaFuncSetAttribute(k_rows, cudaFuncAttributeMaxDynamicSharedMemorySize, smem);

    k_rows<<<MROWS / BM, NTHR, smem>>>(x, W1, b1, g1, be1, W2, b2, g2, be2,
                                       Wa1, ba1, Wa2, ba2);
    k_max<<<NBAG, 256>>>();
    k_wsum<<<NBAG * NCHUNK, 128>>>();
    k_final<<<NBAG, 128>>>(Wc1, bc1, Wc2, bc2, Ws1, bs1, Ws2, bs2, out);
}

// round 5
// speedup vs baseline: 2.4451x; 2.4451x over previous
#include <cuda_runtime.h>
#include <cuda_bf16.h>
#include <math.h>
#include <stdint.h>

// ---------------- problem constants ----------------
#define MROWS   400000
#define NBAG    8
#define NPER    50000
#define DIN     256
#define HDIM    128
#define INV_TAU (1.0f/0.3f)
#define LN_EPS  1e-5f
#define CHUNK   512
#define NCHUNK2 98               // ceil(50000/512)

// ---------------- scratch globals ----------------
__device__ float g_h2[(size_t)MROWS * HDIM];     // 204.8 MB
__device__ float g_scores[MROWS];
__device__ float g_bagmax[NBAG];
__device__ float g_pvec[NBAG * NCHUNK2 * HDIM];
__device__ float g_pZ[NBAG * NCHUNK2];
// bf16 hi/lo weights, dense [n][k]: [W1half0, W1half1, W2, Wa1] x [hi 32KB | lo 32KB]
__device__ __align__(16) unsigned char g_wsw[4 * 65536];

// ---------------- smem layout (bytes) ----------------
// A/B tiles: bf16 [128][136] (8-col pad -> conflict-free ldmatrix)
#define A_HI_OFF 0
#define A_LO_OFF 34816
#define B_HI_OFF 69632
#define B_LO_OFF 104448
#define BIAS_OFF 139264          // 1025 floats
#define SMEM_SZ  143376

__device__ __forceinline__ uint32_t smem_to_u32(const void* p) {
    uint32_t a;
    asm("{ .reg .u64 t; cvta.to.shared.u64 t, %1; cvt.u32.u64 %0, t; }" : "=r"(a) : "l"(p));
    return a;
}

#define LDM4(r, addr) \
    asm volatile("ldmatrix.sync.aligned.m8n8.x4.shared.b16 {%0,%1,%2,%3}, [%4];" \
        : "=r"((r)[0]), "=r"((r)[1]), "=r"((r)[2]), "=r"((r)[3]) : "r"(addr))

#define MMA16816(c, a, b0, b1) \
    asm volatile("mma.sync.aligned.m16n8k16.row.col.f32.bf16.bf16.f32 " \
        "{%0,%1,%2,%3}, {%4,%5,%6,%7}, {%8,%9}, {%0,%1,%2,%3};" \
        : "+f"((c)[0]), "+f"((c)[1]), "+f"((c)[2]), "+f"((c)[3]) \
        : "r"((a)[0]), "r"((a)[1]), "r"((a)[2]), "r"((a)[3]), "r"(b0), "r"(b1))

// ---------------- weight prep: fp32 -> dense bf16 hi/lo [n][k] ----------------
__global__ void k_prep(const float* __restrict__ W1, const float* __restrict__ W2,
                       const float* __restrict__ Wa1)
{
    int mat = blockIdx.x;
    const float* W; int koff;
    if (mat == 0)      { W = W1;  koff = 0;   }
    else if (mat == 1) { W = W1;  koff = 128; }
    else if (mat == 2) { W = W2;  koff = 0;   }
    else               { W = Wa1; koff = 0;   }
    __nv_bfloat16* dh = (__nv_bfloat16*)(g_wsw + (size_t)mat * 65536);
    __nv_bfloat16* dl = dh + 16384;
    for (int idx = threadIdx.x; idx < 16384; idx += blockDim.x) {
        int n = idx >> 7, k = idx & 127;
        float w = W[(size_t)(koff + k) * 128 + n];   // B[n][k] = W[k][n]
        __nv_bfloat16 h = __float2bfloat16(w);
        __nv_bfloat16 l = __float2bfloat16(w - __bfloat162float(h));
        dh[n * 128 + k] = h;
        dl[n * 128 + k] = l;
    }
}

// ---------------- staging helpers ----------------
__device__ __forceinline__ void stage_w(char* sm, int mat, int tid) {
    const uint4* src = (const uint4*)(g_wsw + (size_t)mat * 65536);
#pragma unroll
    for (int i = 0; i < 8; i++) {
        int idx = tid + i * 256;
        int r = idx >> 4, q = idx & 15;
        uint4 vh = src[r * 16 + q];
        uint4 vl = src[2048 + r * 16 + q];
        *(uint4*)(sm + B_HI_OFF + (r * 136 + q * 8) * 2) = vh;
        *(uint4*)(sm + B_LO_OFF + (r * 136 + q * 8) * 2) = vl;
    }
}

__device__ __forceinline__ uint32_t pack_hi(float a, float b, float& la, float& lb) {
    __nv_bfloat16 ha = __float2bfloat16(a), hb = __float2bfloat16(b);
    la = a - __bfloat162float(ha);
    lb = b - __bfloat162float(hb);
    return (uint32_t)__bfloat16_as_ushort(ha) | ((uint32_t)__bfloat16_as_ushort(hb) << 16);
}
__device__ __forceinline__ uint32_t pack_bf(float a, float b) {
    return (uint32_t)__bfloat16_as_ushort(__float2bfloat16(a)) |
           ((uint32_t)__bfloat16_as_ushort(__float2bfloat16(b)) << 16);
}

// stage one K=128 half of x into A hi/lo smem (coalesced float4 loads)
__device__ __forceinline__ void stage_x(char* sm, const float* __restrict__ x,
                                        size_t rowTile, int hh, int tid) {
#pragma unroll
    for (int i = 0; i < 16; i++) {
        int idx = tid + i * 256;
        int r = idx >> 5, c4 = idx & 31;
        float4 vv = *(const float4*)(x + (rowTile + r) * DIN + hh * 128 + c4 * 4);
        float l0, l1, l2, l3;
        uint32_t h0 = pack_hi(vv.x, vv.y, l0, l1);
        uint32_t h1 = pack_hi(vv.z, vv.w, l2, l3);
        uint32_t q0 = pack_bf(l0, l1), q1 = pack_bf(l2, l3);
        uint32_t off = (uint32_t)(r * 136 + c4 * 4) * 2;
        *(uint2*)(sm + A_HI_OFF + off) = make_uint2(h0, h1);
        *(uint2*)(sm + A_LO_OFF + off) = make_uint2(q0, q1);
    }
}

// ---------------- core MMA over one K=128 block (split-bf16, 3 passes) ----------------
__device__ __forceinline__ void mma_block(uint32_t smb, int w, int L, float (*acc)[4]) {
    const uint32_t aRow = (uint32_t)(w * 16 + (L & 15)) * 136u;
    const uint32_t aK0  = 8u * (uint32_t)(L >> 4);
    const int g = L >> 3, rr = L & 7;
    const uint32_t bRow = (uint32_t)((g >> 1) * 8 + rr) * 136u;
    const uint32_t bK0  = 8u * (uint32_t)(g & 1);
#pragma unroll 1
    for (int ks = 0; ks < 8; ks++) {
        uint32_t ah[4], al[4];
        uint32_t aaddr = smb + A_HI_OFF + (aRow + aK0 + (uint32_t)ks * 16u) * 2u;
        LDM4(ah, aaddr);
        LDM4(al, aaddr + (A_LO_OFF - A_HI_OFF));
#pragma unroll
        for (int nt2 = 0; nt2 < 8; nt2++) {
            uint32_t bh[4], bl[4];
            uint32_t baddr = smb + B_HI_OFF +
                (bRow + (uint32_t)nt2 * (16u * 136u) + bK0 + (uint32_t)ks * 16u) * 2u;
            LDM4(bh, baddr);
            LDM4(bl, baddr + (B_LO_OFF - B_HI_OFF));
            MMA16816(acc[2 * nt2],     ah, bh[0], bh[1]);
            MMA16816(acc[2 * nt2 + 1], ah, bh[2], bh[3]);
            MMA16816(acc[2 * nt2],     ah, bl[0], bl[1]);
            MMA16816(acc[2 * nt2 + 1], ah, bl[2], bl[3]);
            MMA16816(acc[2 * nt2],     al, bh[0], bh[1]);
            MMA16816(acc[2 * nt2 + 1], al, bh[2], bh[3]);
        }
    }
}

// ---------------- LN + ReLU epilogue on register fragments ----------------
__device__ __forceinline__ void ln_relu(float (*acc)[4], const float* bias, int boff, int L) {
    const int q2 = 2 * (L & 3);
    float s0 = 0.f, s1 = 0.f;
#pragma unroll
    for (int nt = 0; nt < 16; nt++) {
        int c = nt * 8 + q2;
        float b0 = bias[boff + c], b1v = bias[boff + c + 1];
        acc[nt][0] += b0; acc[nt][1] += b1v; acc[nt][2] += b0; acc[nt][3] += b1v;
        s0 += acc[nt][0] + acc[nt][1];
        s1 += acc[nt][2] + acc[nt][3];
    }
    s0 += __shfl_xor_sync(0xffffffffu, s0, 1); s0 += __shfl_xor_sync(0xffffffffu, s0, 2);
    s1 += __shfl_xor_sync(0xffffffffu, s1, 1); s1 += __shfl_xor_sync(0xffffffffu, s1, 2);
    float mu0 = s0 * 0.0078125f, mu1 = s1 * 0.0078125f;
    float v0 = 0.f, v1 = 0.f;
#pragma unroll
    for (int nt = 0; nt < 16; nt++) {
        float d;
        d = acc[nt][0] - mu0; v0 = fmaf(d, d, v0);
        d = acc[nt][1] - mu0; v0 = fmaf(d, d, v0);
        d = acc[nt][2] - mu1; v1 = fmaf(d, d, v1);
        d = acc[nt][3] - mu1; v1 = fmaf(d, d, v1);
    }
    v0 += __shfl_xor_sync(0xffffffffu, v0, 1); v0 += __shfl_xor_sync(0xffffffffu, v0, 2);
    v1 += __shfl_xor_sync(0xffffffffu, v1, 1); v1 += __shfl_xor_sync(0xffffffffu, v1, 2);
    float i0 = rsqrtf(fmaf(v0, 0.0078125f, LN_EPS));
    float i1 = rsqrtf(fmaf(v1, 0.0078125f, LN_EPS));
#pragma unroll
    for (int nt = 0; nt < 16; nt++) {
        int c = nt * 8 + q2;
        float g0 = bias[boff + 128 + c], g1v = bias[boff + 128 + c + 1];
        float e0 = bias[boff + 256 + c], e1v = bias[boff + 256 + c + 1];
        acc[nt][0] = fmaxf(fmaf((acc[nt][0] - mu0) * i0, g0, e0), 0.f);
        acc[nt][1] = fmaxf(fmaf((acc[nt][1] - mu0) * i0, g1v, e1v), 0.f);
        acc[nt][2] = fmaxf(fmaf((acc[nt][2] - mu1) * i1, g0, e0), 0.f);
        acc[nt][3] = fmaxf(fmaf((acc[nt][3] - mu1) * i1, g1v, e1v), 0.f);
    }
}

// write activated fragments into A hi/lo smem as next-phase A operand
__device__ __forceinline__ void store_A(char* sm, float (*acc)[4], int w, int L) {
    const int r0 = w * 16 + (L >> 2), r1 = r0 + 8;
    const int q2 = 2 * (L & 3);
#pragma unroll
    for (int nt = 0; nt < 16; nt++) {
        int c = nt * 8 + q2;
        float l0, l1;
        uint32_t h = pack_hi(acc[nt][0], acc[nt][1], l0, l1);
        uint32_t l = pack_bf(l0, l1);
        *(uint32_t*)(sm + A_HI_OFF + (r0 * 136 + c) * 2) = h;
        *(uint32_t*)(sm + A_LO_OFF + (r0 * 136 + c) * 2) = l;
        h = pack_hi(acc[nt][2], acc[nt][3], l0, l1);
        l = pack_bf(l0, l1);
        *(uint32_t*)(sm + A_HI_OFF + (r1 * 136 + c) * 2) = h;
        *(uint32_t*)(sm + A_LO_OFF + (r1 * 136 + c) * 2) = l;
    }
}

// ---------------- fused row kernel ----------------
__global__ void __launch_bounds__(256)
k_rows_mma(const float* __restrict__ x,
           const float* __restrict__ b1, const float* __restrict__ g1, const float* __restrict__ be1,
           const float* __restrict__ b2, const float* __restrict__ g2, const float* __restrict__ be2,
           const float* __restrict__ ba1, const float* __restrict__ ba2, const float* __restrict__ Wa2)
{
    extern __shared__ char sm[];
    const uint32_t smb = smem_to_u32(sm);
    const int tid = threadIdx.x;
    const int w = tid >> 5, L = tid & 31;
    const size_t rowTile = (size_t)blockIdx.x * 128;
    float* bias = (float*)(sm + BIAS_OFF);

    if (tid < 128) {
        bias[tid]       = b1[tid];  bias[128 + tid] = g1[tid];  bias[256 + tid] = be1[tid];
        bias[384 + tid] = b2[tid];  bias[512 + tid] = g2[tid];  bias[640 + tid] = be2[tid];
        bias[768 + tid] = ba1[tid]; bias[896 + tid] = Wa2[tid];
    }
    if (tid == 0) bias[1024] = ba2[0];

    float acc[16][4];
#pragma unroll
    for (int nt = 0; nt < 16; nt++)
#pragma unroll
        for (int j = 0; j < 4; j++) acc[nt][j] = 0.f;

    // ===== PHASE 1: x @ W1 (K=256, two K=128 blocks, accumulate in regs) =====
    for (int hh = 0; hh < 2; hh++) {
        stage_x(sm, x, rowTile, hh, tid);
        stage_w(sm, hh, tid);
        __syncthreads();
        mma_block(smb, w, L, acc);
        __syncthreads();
    }
    ln_relu(acc, bias, 0, L);
    stage_w(sm, 2, tid);         // W2
    store_A(sm, acc, w, L);
    __syncthreads();

    // ===== PHASE 2: h1 @ W2 =====
#pragma unroll
    for (int nt = 0; nt < 16; nt++)
#pragma unroll
        for (int j = 0; j < 4; j++) acc[nt][j] = 0.f;
    mma_block(smb, w, L, acc);
    __syncthreads();
    ln_relu(acc, bias, 384, L);

    // stage h2 fp32 through B region (free now), then coalesced gmem store
    {
        float* Bf = (float*)(sm + B_HI_OFF);
        const int r0 = w * 16 + (L >> 2), r1 = r0 + 8;
        const int q2 = 2 * (L & 3);
#pragma unroll
        for (int nt = 0; nt < 16; nt++) {
            int c = nt * 8 + q2;
            Bf[r0 * 132 + c]     = acc[nt][0];
            Bf[r0 * 132 + c + 1] = acc[nt][1];
            Bf[r1 * 132 + c]     = acc[nt][2];
            Bf[r1 * 132 + c + 1] = acc[nt][3];
        }
        store_A(sm, acc, w, L);
        __syncthreads();
#pragma unroll
        for (int i = 0; i < 16; i++) {
            int idx = tid + i * 256;
            int r = idx >> 5, c4 = idx & 31;
            float4 vv = make_float4(Bf[r * 132 + c4 * 4],     Bf[r * 132 + c4 * 4 + 1],
                                    Bf[r * 132 + c4 * 4 + 2], Bf[r * 132 + c4 * 4 + 3]);
            *(float4*)(g_h2 + (rowTile + r) * HDIM + c4 * 4) = vv;
        }
        __syncthreads();
    }
    stage_w(sm, 3, tid);         // Wa1
    __syncthreads();

    // ===== PHASE 3: h2 @ Wa1 -> tanh -> dot Wa2 -> scores =====
#pragma unroll
    for (int nt = 0; nt < 16; nt++)
#pragma unroll
        for (int j = 0; j < 4; j++) acc[nt][j] = 0.f;
    mma_block(smb, w, L, acc);

    {
        const int r0 = w * 16 + (L >> 2), r1 = r0 + 8;
        const int q2 = 2 * (L & 3);
        float p0 = 0.f, p1 = 0.f;
#pragma unroll
        for (int nt = 0; nt < 16; nt++) {
            int c = nt * 8 + q2;
            float wa0 = bias[896 + c], wa1v = bias[896 + c + 1];
            float bb0 = bias[768 + c], bb1 = bias[768 + c + 1];
            p0 = fmaf(tanhf(acc[nt][0] + bb0), wa0, p0);
            p0 = fmaf(tanhf(acc[nt][1] + bb1), wa1v, p0);
            p1 = fmaf(tanhf(acc[nt][2] + bb0), wa0, p1);
            p1 = fmaf(tanhf(acc[nt][3] + bb1), wa1v, p1);
        }
        p0 += __shfl_xor_sync(0xffffffffu, p0, 1); p0 += __shfl_xor_sync(0xffffffffu, p0, 2);
        p1 += __shfl_xor_sync(0xffffffffu, p1, 1); p1 += __shfl_xor_sync(0xffffffffu, p1, 2);
        if ((L & 3) == 0) {
            float bb = bias[1024];
            g_scores[rowTile + r0] = p0 + bb;
            g_scores[rowTile + r1] = p1 + bb;
        }
    }
}

// ---------------- per-bag score max ----------------
__global__ __launch_bounds__(256)
void k_max()
{
    const int bag = blockIdx.x;
    const int tid = threadIdx.x;
    __shared__ float red[256];
    float m = -3.4e38f;
    const float* sp = g_scores + (size_t)bag * NPER;
    for (int i = tid; i < NPER; i += 256) m = fmaxf(m, sp[i]);
    red[tid] = m;
    __syncthreads();
    for (int off = 128; off; off >>= 1) {
        if (tid < off) red[tid] = fmaxf(red[tid], red[tid + off]);
        __syncthreads();
    }
    if (tid == 0) g_bagmax[bag] = red[0];
}

// ---------------- weighted partial sums (chunks of 512 rows) ----------------
__global__ __launch_bounds__(128)
void k_wsum()
{
    const int b = blockIdx.x / NCHUNK2;
    const int c = blockIdx.x % NCHUNK2;
    const int tid = threadIdx.x;
    const int base = c * CHUNK;
    const int cnt = min(CHUNK, NPER - base);
    __shared__ float wrow[CHUNK];

    const float bm = g_bagmax[b];
    for (int i = tid; i < CHUNK; i += 128) {
        float w = 0.0f;
        if (i < cnt) w = expf((g_scores[(size_t)b * NPER + base + i] - bm) * INV_TAU);
        wrow[i] = w;
    }
    __syncthreads();

    float a0 = 0.f, a1 = 0.f, a2 = 0.f, a3 = 0.f;
    const float* hp = g_h2 + ((size_t)b * NPER + base) * HDIM + tid;
    int n = 0;
    for (; n + 4 <= cnt; n += 4) {
        a0 = fmaf(wrow[n],     hp[(size_t)n * HDIM], a0);
        a1 = fmaf(wrow[n + 1], hp[(size_t)(n + 1) * HDIM], a1);
        a2 = fmaf(wrow[n + 2], hp[(size_t)(n + 2) * HDIM], a2);
        a3 = fmaf(wrow[n + 3], hp[(size_t)(n + 3) * HDIM], a3);
    }
    for (; n < cnt; n++) a0 = fmaf(wrow[n], hp[(size_t)n * HDIM], a0);
    g_pvec[((size_t)b * NCHUNK2 + c) * HDIM + tid] = (a0 + a1) + (a2 + a3);

    __syncthreads();
    float z = wrow[tid] + wrow[tid + 128] + wrow[tid + 256] + wrow[tid + 384];
    wrow[tid] = z;
    __syncthreads();
    for (int off = 64; off; off >>= 1) {
        if (tid < off) wrow[tid] += wrow[tid + off];
        __syncthreads();
    }
    if (tid == 0) g_pZ[b * NCHUNK2 + c] = wrow[0];
}

// ---------------- final heads ----------------
__global__ __launch_bounds__(128)
void k_final(const float* __restrict__ Wc1, const float* __restrict__ bc1,
             const float* __restrict__ Wc2, const float* __restrict__ bc2,
             const float* __restrict__ Ws1, const float* __restrict__ bs1,
             const float* __restrict__ Ws2, const float* __restrict__ bs2,
             float* __restrict__ out)
{
    const int bag = blockIdx.x;
    const int tid = threadIdx.x;
    __shared__ float bagn[128];
    __shared__ float hid[128];
    __shared__ float redz[128];
    __shared__ float hs[64];

    float vv = 0.0f;
    for (int c = 0; c < NCHUNK2; c++)
        vv += g_pvec[((size_t)bag * NCHUNK2 + c) * HDIM + tid];

    float zp = 0.0f;
    for (int c = tid; c < NCHUNK2; c += 128)
        zp += g_pZ[bag * NCHUNK2 + c];
    redz[tid] = zp;
    __syncthreads();
    for (int off = 64; off; off >>= 1) {
        if (tid < off) redz[tid] += redz[tid + off];
        __syncthreads();
    }
    const float Z = redz[0];
    bagn[tid] = vv / Z;
    __syncthreads();

    {
        float h = bc1[tid];
        for (int k = 0; k < 128; k++) h = fmaf(bagn[k], Wc1[k * 128 + tid], h);
        hid[tid] = fmaxf(h, 0.0f);
    }
    if (tid < 64) {
        float h = bs1[tid];
        for (int k = 0; k < 128; k++) h = fmaf(bagn[k], Ws1[k * 64 + tid], h);
        hs[tid] = fmaxf(h, 0.0f);
    }
    __syncthreads();

    if (tid < 2) {
        float s = bc2[tid];
        for (int j = 0; j < 128; j++) s = fmaf(hid[j], Wc2[j * 2 + tid], s);
        out[bag * 2 + tid] = s;
    }
    if (tid == 2) {
        float r = bs2[0];
        for (int j = 0; j < 64; j++) r = fmaf(hs[j], Ws2[j], r);
        out[16 + bag] = r;
    }
}

extern "C" void kernel_launch(void* const* d_in, const int* in_sizes, int n_in,
                              void* d_out, int out_size)
{
    const float* x   = (const float*)d_in[0];
    const float* W1  = (const float*)d_in[1];
    const float* b1  = (const float*)d_in[2];
    const float* g1  = (const float*)d_in[3];
    const float* be1 = (const float*)d_in[4];
    const float* W2  = (const float*)d_in[5];
    const float* b2  = (const float*)d_in[6];
    const float* g2  = (const float*)d_in[7];
    const float* be2 = (const float*)d_in[8];
    const float* Wa1 = (const float*)d_in[9];
    const float* ba1 = (const float*)d_in[10];
    const float* Wa2 = (const float*)d_in[11];
    const float* ba2 = (const float*)d_in[12];
    const float* Wc1 = (const float*)d_in[13];
    const float* bc1 = (const float*)d_in[14];
    const float* Wc2 = (const float*)d_in[15];
    const float* bc2 = (const float*)d_in[16];
    const float* Ws1 = (const float*)d_in[17];
    const float* bs1 = (const float*)d_in[18];
    const float* Ws2 = (const float*)d_in[19];
    const float* bs2 = (const float*)d_in[20];
    float* out = (float*)d_out;

    cudaFuncSetAttribute(k_rows_mma, cudaFuncAttributeMaxDynamicSharedMemorySize, SMEM_SZ);

    k_prep<<<4, 256>>>(W1, W2, Wa1);
    k_rows_mma<<<MROWS / 128, 256, SMEM_SZ>>>(x, b1, g1, be1, b2, g2, be2, ba1, ba2, Wa2);
    k_max<<<NBAG, 256>>>();
    k_wsum<<<NBAG * NCHUNK2, 128>>>();
    k_final<<<NBAG, 128>>>(Wc1, bc1, Wc2, bc2, Ws1, bs1, Ws2, bs2, out);
}

// round 6
// speedup vs baseline: 2.8884x; 1.1813x over previous
#include <cuda_runtime.h>
#include <cuda_bf16.h>
#include <math.h>
#include <stdint.h>

// ---------------- problem constants ----------------
#define MROWS   400000
#define NBAG    8
#define NPER    50000
#define DIN     256
#define HDIM    128
#define INV_TAU (1.0f/0.3f)
#define LN_EPS  1e-5f
#define CHUNK   512
#define NCHUNK2 98               // ceil(50000/512)

// ---------------- scratch globals ----------------
__device__ __nv_bfloat16 g_h2b[(size_t)MROWS * HDIM];   // 102.4 MB (bf16)
__device__ float g_scores[MROWS];
__device__ float g_bagmax[NBAG];
__device__ float g_pvec[NBAG * NCHUNK2 * HDIM];
__device__ float g_pZ[NBAG * NCHUNK2];
// bf16 hi/lo weights, dense [n][k]: [W1half0, W1half1, W2, Wa1] x [hi 32KB | lo 32KB]
__device__ __align__(16) unsigned char g_wsw[4 * 65536];

// ---------------- smem layout (bytes) ----------------
// A tile: bf16 [128][136] hi+lo; B tiles double-buffered hi+lo
#define A_HI_OFF  0
#define A_LO_OFF  34816
#define B0_OFF    69632          // hi at +0, lo at +34816
#define B1_OFF    139264
#define BIAS_OFF  208896         // 1025 floats
#define SMEM_SZ   213000
#define BLO       34816          // hi->lo offset within a B buffer

__device__ __forceinline__ uint32_t smem_to_u32(const void* p) {
    uint32_t a;
    asm("{ .reg .u64 t; cvta.to.shared.u64 t, %1; cvt.u32.u64 %0, t; }" : "=r"(a) : "l"(p));
    return a;
}

#define LDM4(r, addr) \
    asm volatile("ldmatrix.sync.aligned.m8n8.x4.shared.b16 {%0,%1,%2,%3}, [%4];" \
        : "=r"((r)[0]), "=r"((r)[1]), "=r"((r)[2]), "=r"((r)[3]) : "r"(addr))

#define MMA16816(c, a, b0, b1) \
    asm volatile("mma.sync.aligned.m16n8k16.row.col.f32.bf16.bf16.f32 " \
        "{%0,%1,%2,%3}, {%4,%5,%6,%7}, {%8,%9}, {%0,%1,%2,%3};" \
        : "+f"((c)[0]), "+f"((c)[1]), "+f"((c)[2]), "+f"((c)[3]) \
        : "r"((a)[0]), "r"((a)[1]), "r"((a)[2]), "r"((a)[3]), "r"(b0), "r"(b1))

#define CP_ASYNC16(saddr, gptr) \
    asm volatile("cp.async.cg.shared.global [%0], [%1], 16;" :: "r"(saddr), "l"(gptr) : "memory")
#define CP_COMMIT() asm volatile("cp.async.commit_group;" ::: "memory")
#define CP_WAIT(n)  asm volatile("cp.async.wait_group %0;" :: "n"(n) : "memory")

// exact identity tanh: (e^{2x}-1)/(e^{2x}+1) = 1 - 2/(e^{2x}+1); abs err ~1e-7
__device__ __forceinline__ float fast_tanh(float x) {
    float e = __expf(2.0f * x);
    return 1.0f - __fdividef(2.0f, e + 1.0f);
}

// ---------------- weight prep: fp32 -> dense bf16 hi/lo [n][k] ----------------
__global__ void k_prep(const float* __restrict__ W1, const float* __restrict__ W2,
                       const float* __restrict__ Wa1)
{
    int mat = blockIdx.x;
    const float* W; int koff;
    if (mat == 0)      { W = W1;  koff = 0;   }
    else if (mat == 1) { W = W1;  koff = 128; }
    else if (mat == 2) { W = W2;  koff = 0;   }
    else               { W = Wa1; koff = 0;   }
    __nv_bfloat16* dh = (__nv_bfloat16*)(g_wsw + (size_t)mat * 65536);
    __nv_bfloat16* dl = dh + 16384;
    for (int idx = threadIdx.x; idx < 16384; idx += blockDim.x) {
        int n = idx >> 7, k = idx & 127;
        float w = W[(size_t)(koff + k) * 128 + n];   // B[n][k] = W[k][n]
        __nv_bfloat16 h = __float2bfloat16(w);
        __nv_bfloat16 l = __float2bfloat16(w - __bfloat162float(h));
        dh[n * 128 + k] = h;
        dl[n * 128 + k] = l;
    }
}

// ---------------- staging ----------------
// async weight stage: dense [128][128] bf16 -> padded [128][136] smem, hi+lo
__device__ __forceinline__ void stage_w_async(uint32_t smb, int mat, uint32_t dstoff, int tid) {
    const unsigned char* src = g_wsw + (size_t)mat * 65536;
    unsigned long long gbase = (unsigned long long)__cvta_generic_to_global((void*)src);
#pragma unroll
    for (int i = 0; i < 8; i++) {
        int idx = tid + i * 256;
        int r = idx >> 4, q = idx & 15;
        uint32_t soff = (uint32_t)(r * 136 + q * 8) * 2u;
        unsigned long long goff = (unsigned long long)(r * 128 + q * 8) * 2ull;
        CP_ASYNC16(smb + dstoff + soff,        gbase + goff);
        CP_ASYNC16(smb + dstoff + BLO + soff,  gbase + 32768ull + goff);
    }
}

__device__ __forceinline__ uint32_t pack_hi(float a, float b, float& la, float& lb) {
    __nv_bfloat16 ha = __float2bfloat16(a), hb = __float2bfloat16(b);
    la = a - __bfloat162float(ha);
    lb = b - __bfloat162float(hb);
    return (uint32_t)__bfloat16_as_ushort(ha) | ((uint32_t)__bfloat16_as_ushort(hb) << 16);
}
__device__ __forceinline__ uint32_t pack_bf(float a, float b) {
    return (uint32_t)__bfloat16_as_ushort(__float2bfloat16(a)) |
           ((uint32_t)__bfloat16_as_ushort(__float2bfloat16(b)) << 16);
}

// stage one K=128 half of x into A hi/lo smem (coalesced float4 loads)
__device__ __forceinline__ void stage_x(char* sm, const float* __restrict__ x,
                                        size_t rowTile, int hh, int tid) {
#pragma unroll
    for (int i = 0; i < 16; i++) {
        int idx = tid + i * 256;
        int r = idx >> 5, c4 = idx & 31;
        float4 vv = *(const float4*)(x + (rowTile + r) * DIN + hh * 128 + c4 * 4);
        float l0, l1, l2, l3;
        uint32_t h0 = pack_hi(vv.x, vv.y, l0, l1);
        uint32_t h1 = pack_hi(vv.z, vv.w, l2, l3);
        uint32_t q0 = pack_bf(l0, l1), q1 = pack_bf(l2, l3);
        uint32_t off = (uint32_t)(r * 136 + c4 * 4) * 2;
        *(uint2*)(sm + A_HI_OFF + off) = make_uint2(h0, h1);
        *(uint2*)(sm + A_LO_OFF + off) = make_uint2(q0, q1);
    }
}

// ---------------- core MMA over one K=128 block (split-bf16, 3 passes) ----------------
__device__ __forceinline__ void mma_block(uint32_t smb, uint32_t boff, int w, int L, float (*acc)[4]) {
    const uint32_t aRow = (uint32_t)(w * 16 + (L & 15)) * 136u;
    const uint32_t aK0  = 8u * (uint32_t)(L >> 4);
    const int g = L >> 3, rr = L & 7;
    const uint32_t bRow = (uint32_t)((g >> 1) * 8 + rr) * 136u;
    const uint32_t bK0  = 8u * (uint32_t)(g & 1);
#pragma unroll 2
    for (int ks = 0; ks < 8; ks++) {
        uint32_t ah[4], al[4];
        uint32_t aaddr = smb + A_HI_OFF + (aRow + aK0 + (uint32_t)ks * 16u) * 2u;
        LDM4(ah, aaddr);
        LDM4(al, aaddr + (A_LO_OFF - A_HI_OFF));
#pragma unroll
        for (int nt2 = 0; nt2 < 8; nt2++) {
            uint32_t bh[4], bl[4];
            uint32_t baddr = smb + boff +
                (bRow + (uint32_t)nt2 * (16u * 136u) + bK0 + (uint32_t)ks * 16u) * 2u;
            LDM4(bh, baddr);
            LDM4(bl, baddr + BLO);
            MMA16816(acc[2 * nt2],     ah, bh[0], bh[1]);
            MMA16816(acc[2 * nt2 + 1], ah, bh[2], bh[3]);
            MMA16816(acc[2 * nt2],     ah, bl[0], bl[1]);
            MMA16816(acc[2 * nt2 + 1], ah, bl[2], bl[3]);
            MMA16816(acc[2 * nt2],     al, bh[0], bh[1]);
            MMA16816(acc[2 * nt2 + 1], al, bh[2], bh[3]);
        }
    }
}

// ---------------- LN + ReLU epilogue on register fragments ----------------
__device__ __forceinline__ void ln_relu(float (*acc)[4], const float* bias, int boff, int L) {
    const int q2 = 2 * (L & 3);
    float s0 = 0.f, s1 = 0.f;
#pragma unroll
    for (int nt = 0; nt < 16; nt++) {
        int c = nt * 8 + q2;
        float b0 = bias[boff + c], b1v = bias[boff + c + 1];
        acc[nt][0] += b0; acc[nt][1] += b1v; acc[nt][2] += b0; acc[nt][3] += b1v;
        s0 += acc[nt][0] + acc[nt][1];
        s1 += acc[nt][2] + acc[nt][3];
    }
    s0 += __shfl_xor_sync(0xffffffffu, s0, 1); s0 += __shfl_xor_sync(0xffffffffu, s0, 2);
    s1 += __shfl_xor_sync(0xffffffffu, s1, 1); s1 += __shfl_xor_sync(0xffffffffu, s1, 2);
    float mu0 = s0 * 0.0078125f, mu1 = s1 * 0.0078125f;
    float v0 = 0.f, v1 = 0.f;
#pragma unroll
    for (int nt = 0; nt < 16; nt++) {
        float d;
        d = acc[nt][0] - mu0; v0 = fmaf(d, d, v0);
        d = acc[nt][1] - mu0; v0 = fmaf(d, d, v0);
        d = acc[nt][2] - mu1; v1 = fmaf(d, d, v1);
        d = acc[nt][3] - mu1; v1 = fmaf(d, d, v1);
    }
    v0 += __shfl_xor_sync(0xffffffffu, v0, 1); v0 += __shfl_xor_sync(0xffffffffu, v0, 2);
    v1 += __shfl_xor_sync(0xffffffffu, v1, 1); v1 += __shfl_xor_sync(0xffffffffu, v1, 2);
    float i0 = rsqrtf(fmaf(v0, 0.0078125f, LN_EPS));
    float i1 = rsqrtf(fmaf(v1, 0.0078125f, LN_EPS));
#pragma unroll
    for (int nt = 0; nt < 16; nt++) {
        int c = nt * 8 + q2;
        float g0 = bias[boff + 128 + c], g1v = bias[boff + 128 + c + 1];
        float e0 = bias[boff + 256 + c], e1v = bias[boff + 256 + c + 1];
        acc[nt][0] = fmaxf(fmaf((acc[nt][0] - mu0) * i0, g0, e0), 0.f);
        acc[nt][1] = fmaxf(fmaf((acc[nt][1] - mu0) * i0, g1v, e1v), 0.f);
        acc[nt][2] = fmaxf(fmaf((acc[nt][2] - mu1) * i1, g0, e0), 0.f);
        acc[nt][3] = fmaxf(fmaf((acc[nt][3] - mu1) * i1, g1v, e1v), 0.f);
    }
}

// write activated fragments into A hi/lo smem as next-phase A operand
__device__ __forceinline__ void store_A(char* sm, float (*acc)[4], int w, int L) {
    const int r0 = w * 16 + (L >> 2), r1 = r0 + 8;
    const int q2 = 2 * (L & 3);
#pragma unroll
    for (int nt = 0; nt < 16; nt++) {
        int c = nt * 8 + q2;
        float l0, l1;
        uint32_t h = pack_hi(acc[nt][0], acc[nt][1], l0, l1);
        uint32_t l = pack_bf(l0, l1);
        *(uint32_t*)(sm + A_HI_OFF + (r0 * 136 + c) * 2) = h;
        *(uint32_t*)(sm + A_LO_OFF + (r0 * 136 + c) * 2) = l;
        h = pack_hi(acc[nt][2], acc[nt][3], l0, l1);
        l = pack_bf(l0, l1);
        *(uint32_t*)(sm + A_HI_OFF + (r1 * 136 + c) * 2) = h;
        *(uint32_t*)(sm + A_LO_OFF + (r1 * 136 + c) * 2) = l;
    }
}

// ---------------- fused row kernel ----------------
__global__ void __launch_bounds__(256)
k_rows_mma(const float* __restrict__ x,
           const float* __restrict__ b1, const float* __restrict__ g1, const float* __restrict__ be1,
           const float* __restrict__ b2, const float* __restrict__ g2, const float* __restrict__ be2,
           const float* __restrict__ ba1, const float* __restrict__ ba2, const float* __restrict__ Wa2)
{
    extern __shared__ char sm[];
    const uint32_t smb = smem_to_u32(sm);
    const int tid = threadIdx.x;
    const int w = tid >> 5, L = tid & 31;
    const size_t rowTile = (size_t)blockIdx.x * 128;
    float* bias = (float*)(sm + BIAS_OFF);

    // issue async weight prefetch for the first two B buffers immediately
    stage_w_async(smb, 0, B0_OFF, tid); CP_COMMIT();   // G0: W1 half0
    stage_w_async(smb, 1, B1_OFF, tid); CP_COMMIT();   // G1: W1 half1

    if (tid < 128) {
        bias[tid]       = b1[tid];  bias[128 + tid] = g1[tid];  bias[256 + tid] = be1[tid];
        bias[384 + tid] = b2[tid];  bias[512 + tid] = g2[tid];  bias[640 + tid] = be2[tid];
        bias[768 + tid] = ba1[tid]; bias[896 + tid] = Wa2[tid];
    }
    if (tid == 0) bias[1024] = ba2[0];

    float acc[16][4];
#pragma unroll
    for (int nt = 0; nt < 16; nt++)
#pragma unroll
        for (int j = 0; j < 4; j++) acc[nt][j] = 0.f;

    // ===== PHASE 1: x @ W1 (K=256, two K=128 blocks, accumulate in regs) =====
    stage_x(sm, x, rowTile, 0, tid);
    CP_WAIT(1);                   // G0 (W1h0) complete, G1 may be in flight
    __syncthreads();
    mma_block(smb, B0_OFF, w, L, acc);
    __syncthreads();              // A + B0 free
    stage_w_async(smb, 2, B0_OFF, tid); CP_COMMIT();   // G2: W2, overlaps x1+mma1
    stage_x(sm, x, rowTile, 1, tid);
    CP_WAIT(1);                   // G1 (W1h1) complete
    __syncthreads();
    mma_block(smb, B1_OFF, w, L, acc);
    __syncthreads();              // B1 free
    stage_w_async(smb, 3, B1_OFF, tid); CP_COMMIT();   // G3: Wa1, overlaps epi1+mma2

    ln_relu(acc, bias, 0, L);
    store_A(sm, acc, w, L);
    CP_WAIT(1);                   // G2 (W2) complete
    __syncthreads();

    // ===== PHASE 2: h1 @ W2 =====
#pragma unroll
    for (int nt = 0; nt < 16; nt++)
#pragma unroll
        for (int j = 0; j < 4; j++) acc[nt][j] = 0.f;
    mma_block(smb, B0_OFF, w, L, acc);
    __syncthreads();              // B0 (and A) free for reuse
    ln_relu(acc, bias, 384, L);

    // stage h2 bf16 through B0 region, coalesced store to g_h2b; refresh A
    {
        uint32_t* Hs = (uint32_t*)(sm + B0_OFF);     // [128][68] uints (bf16x2)
        const int r0 = w * 16 + (L >> 2), r1 = r0 + 8;
        const int qq = (L & 3);
#pragma unroll
        for (int nt = 0; nt < 16; nt++) {
            int cu = nt * 4 + qq;
            Hs[r0 * 68 + cu] = pack_bf(acc[nt][0], acc[nt][1]);
            Hs[r1 * 68 + cu] = pack_bf(acc[nt][2], acc[nt][3]);
        }
        store_A(sm, acc, w, L);
        CP_WAIT(0);               // G3 (Wa1) complete
        __syncthreads();
#pragma unroll
        for (int i = 0; i < 8; i++) {
            int idx = tid + i * 256;
            int r = idx >> 4, q = idx & 15;          // 16 uint4 per 128-bf16 row
            uint4 vv = *(uint4*)(Hs + r * 68 + q * 4);
            *(uint4*)((char*)(g_h2b + (rowTile + r) * HDIM) + q * 16) = vv;
        }
    }

    // ===== PHASE 3: h2 @ Wa1 -> tanh -> dot Wa2 -> scores =====
#pragma unroll
    for (int nt = 0; nt < 16; nt++)
#pragma unroll
        for (int j = 0; j < 4; j++) acc[nt][j] = 0.f;
    mma_block(smb, B1_OFF, w, L, acc);

    {
        const int r0 = w * 16 + (L >> 2), r1 = r0 + 8;
        const int q2 = 2 * (L & 3);
        float p0 = 0.f, p1 = 0.f;
#pragma unroll
        for (int nt = 0; nt < 16; nt++) {
            int c = nt * 8 + q2;
            float wa0 = bias[896 + c], wa1v = bias[896 + c + 1];
            float bb0 = bias[768 + c], bb1 = bias[768 + c + 1];
            p0 = fmaf(fast_tanh(acc[nt][0] + bb0), wa0, p0);
            p0 = fmaf(fast_tanh(acc[nt][1] + bb1), wa1v, p0);
            p1 = fmaf(fast_tanh(acc[nt][2] + bb0), wa0, p1);
            p1 = fmaf(fast_tanh(acc[nt][3] + bb1), wa1v, p1);
        }
        p0 += __shfl_xor_sync(0xffffffffu, p0, 1); p0 += __shfl_xor_sync(0xffffffffu, p0, 2);
        p1 += __shfl_xor_sync(0xffffffffu, p1, 1); p1 += __shfl_xor_sync(0xffffffffu, p1, 2);
        if ((L & 3) == 0) {
            float bb = bias[1024];
            g_scores[rowTile + r0] = p0 + bb;
            g_scores[rowTile + r1] = p1 + bb;
        }
    }
}

// ---------------- per-bag score max ----------------
__global__ __launch_bounds__(256)
void k_max()
{
    const int bag = blockIdx.x;
    const int tid = threadIdx.x;
    __shared__ float red[256];
    float m = -3.4e38f;
    const float* sp = g_scores + (size_t)bag * NPER;
    for (int i = tid; i < NPER; i += 256) m = fmaxf(m, sp[i]);
    red[tid] = m;
    __syncthreads();
    for (int off = 128; off; off >>= 1) {
        if (tid < off) red[tid] = fmaxf(red[tid], red[tid + off]);
        __syncthreads();
    }
    if (tid == 0) g_bagmax[bag] = red[0];
}

// ---------------- weighted partial sums (chunks of 512 rows, bf16 h2) ----------------
__global__ __launch_bounds__(256)
void k_wsum()
{
    const int b = blockIdx.x / NCHUNK2;
    const int c = blockIdx.x % NCHUNK2;
    const int tid = threadIdx.x;
    const int base = c * CHUNK;
    const int cnt = min(CHUNK, NPER - base);
    __shared__ float wrow[CHUNK];
    __shared__ float2 sred[256];

    const float bm = g_bagmax[b];
    {
        int i0 = tid, i1 = tid + 256;
        wrow[i0] = (i0 < cnt) ? expf((g_scores[(size_t)b * NPER + base + i0] - bm) * INV_TAU) : 0.f;
        wrow[i1] = (i1 < cnt) ? expf((g_scores[(size_t)b * NPER + base + i1] - bm) * INV_TAU) : 0.f;
    }
    __syncthreads();

    const int c2 = tid & 63;     // bf16x2 column pair
    const int rg = tid >> 6;     // 0..3 row groups
    const uint32_t* hp = (const uint32_t*)(g_h2b + ((size_t)b * NPER + base) * HDIM) + c2;

    float2 a0 = {0.f,0.f}, a1 = {0.f,0.f}, a2 = {0.f,0.f}, a3 = {0.f,0.f};
    int n = rg;
    for (; n + 12 < cnt; n += 16) {
        uint32_t u0 = hp[(size_t)n * 64];
        uint32_t u1 = hp[(size_t)(n + 4) * 64];
        uint32_t u2 = hp[(size_t)(n + 8) * 64];
        uint32_t u3 = hp[(size_t)(n + 12) * 64];
        float2 f0 = __bfloat1622float2(*(const __nv_bfloat162*)&u0);
        float2 f1 = __bfloat1622float2(*(const __nv_bfloat162*)&u1);
        float2 f2 = __bfloat1622float2(*(const __nv_bfloat162*)&u2);
        float2 f3 = __bfloat1622float2(*(const __nv_bfloat162*)&u3);
        float w0 = wrow[n], w1 = wrow[n + 4], w2 = wrow[n + 8], w3 = wrow[n + 12];
        a0.x = fmaf(w0, f0.x, a0.x); a0.y = fmaf(w0, f0.y, a0.y);
        a1.x = fmaf(w1, f1.x, a1.x); a1.y = fmaf(w1, f1.y, a1.y);
        a2.x = fmaf(w2, f2.x, a2.x); a2.y = fmaf(w2, f2.y, a2.y);
        a3.x = fmaf(w3, f3.x, a3.x); a3.y = fmaf(w3, f3.y, a3.y);
    }
    for (; n < cnt; n += 4) {
        uint32_t u = hp[(size_t)n * 64];
        float2 f = __bfloat1622float2(*(const __nv_bfloat162*)&u);
        float wv = wrow[n];
        a0.x = fmaf(wv, f.x, a0.x); a0.y = fmaf(wv, f.y, a0.y);
    }
    float2 at;
    at.x = (a0.x + a1.x) + (a2.x + a3.x);
    at.y = (a0.y + a1.y) + (a2.y + a3.y);
    sred[tid] = at;
    __syncthreads();
    if (tid < 64) {
        float2 t0 = sred[tid], t1 = sred[tid + 64], t2 = sred[tid + 128], t3 = sred[tid + 192];
        float* pv = g_pvec + ((size_t)b * NCHUNK2 + c) * HDIM;
        pv[2 * tid]     = (t0.x + t1.x) + (t2.x + t3.x);
        pv[2 * tid + 1] = (t0.y + t1.y) + (t2.y + t3.y);
    }

    // Z partial
    __syncthreads();
    float z = wrow[tid] + wrow[tid + 256];
    wrow[tid] = z;
    __syncthreads();
    for (int off = 128; off; off >>= 1) {
        if (tid < off) wrow[tid] += wrow[tid + off];
        __syncthreads();
    }
    if (tid == 0) g_pZ[b * NCHUNK2 + c] = wrow[0];
}

// ---------------- final heads ----------------
__global__ __launch_bounds__(128)
void k_final(const float* __restrict__ Wc1, const float* __restrict__ bc1,
             const float* __restrict__ Wc2, const float* __restrict__ bc2,
             const float* __restrict__ Ws1, const float* __restrict__ bs1,
             const float* __restrict__ Ws2, const float* __restrict__ bs2,
             float* __restrict__ out)
{
    const int bag = blockIdx.x;
    const int tid = threadIdx.x;
    __shared__ float bagn[128];
    __shared__ float hid[128];
    __shared__ float redz[128];
    __shared__ float hs[64];

    float vv = 0.0f;
    for (int c = 0; c < NCHUNK2; c++)
        vv += g_pvec[((size_t)bag * NCHUNK2 + c) * HDIM + tid];

    float zp = 0.0f;
    for (int c = tid; c < NCHUNK2; c += 128)
        zp += g_pZ[bag * NCHUNK2 + c];
    redz[tid] = zp;
    __syncthreads();
    for (int off = 64; off; off >>= 1) {
        if (tid < off) redz[tid] += redz[tid + off];
        __syncthreads();
    }
    const float Z = redz[0];
    bagn[tid] = vv / Z;
    __syncthreads();

    {
        float h = bc1[tid];
        for (int k = 0; k < 128; k++) h = fmaf(bagn[k], Wc1[k * 128 + tid], h);
        hid[tid] = fmaxf(h, 0.0f);
    }
    if (tid < 64) {
        float h = bs1[tid];
        for (int k = 0; k < 128; k++) h = fmaf(bagn[k], Ws1[k * 64 + tid], h);
        hs[tid] = fmaxf(h, 0.0f);
    }
    __syncthreads();

    if (tid < 2) {
        float s = bc2[tid];
        for (int j = 0; j < 128; j++) s = fmaf(hid[j], Wc2[j * 2 + tid], s);
        out[bag * 2 + tid] = s;
    }
    if (tid == 2) {
        float r = bs2[0];
        for (int j = 0; j < 64; j++) r = fmaf(hs[j], Ws2[j], r);
        out[16 + bag] = r;
    }
}

extern "C" void kernel_launch(void* const* d_in, const int* in_sizes, int n_in,
                              void* d_out, int out_size)
{
    const float* x   = (const float*)d_in[0];
    const float* W1  = (const float*)d_in[1];
    const float* b1  = (const float*)d_in[2];
    const float* g1  = (const float*)d_in[3];
    const float* be1 = (const float*)d_in[4];
    const float* W2  = (const float*)d_in[5];
    const float* b2  = (const float*)d_in[6];
    const float* g2  = (const float*)d_in[7];
    const float* be2 = (const float*)d_in[8];
    const float* Wa1 = (const float*)d_in[9];
    const float* ba1 = (const float*)d_in[10];
    const float* Wa2 = (const float*)d_in[11];
    const float* ba2 = (const float*)d_in[12];
    const float* Wc1 = (const float*)d_in[13];
    const float* bc1 = (const float*)d_in[14];
    const float* Wc2 = (const float*)d_in[15];
    const float* bc2 = (const float*)d_in[16];
    const float* Ws1 = (const float*)d_in[17];
    const float* bs1 = (const float*)d_in[18];
    const float* Ws2 = (const float*)d_in[19];
    const float* bs2 = (const float*)d_in[20];
    float* out = (float*)d_out;

    cudaFuncSetAttribute(k_rows_mma, cudaFuncAttributeMaxDynamicSharedMemorySize, SMEM_SZ);

    k_prep<<<4, 256>>>(W1, W2, Wa1);
    k_rows_mma<<<MROWS / 128, 256, SMEM_SZ>>>(x, b1, g1, be1, b2, g2, be2, ba1, ba2, Wa2);
    k_max<<<NBAG, 256>>>();
    k_wsum<<<NBAG * NCHUNK2, 256>>>();
    k_final<<<NBAG, 128>>>(Wc1, bc1, Wc2, bc2, Ws1, bs1, Ws2, bs2, out);
}